// round 16
// baseline (speedup 1.0000x reference)
#include <cuda_runtime.h>
#include <cuda_bf16.h>
#include <cstdint>

// ---------------------------------------------------------------------------
// 2-layer GCN, CSR-by-dst gather formulation:
//   deg[i] = 1 + in_degree(i);  dinv = rsqrt(deg)
//   h' = dinv ⊙ (X @ W)            (tf32x3 tensor-core GEMM, scaled write)
//   out[d] = relu(dinv[d] * (h'[d] + sum_{s in nbr(d)} h'[s]) + b)   (gather)
// GEMM smem holds fp32 pairs (v[k], v[k+4]) per float2, row stride 136
// (mod 32 = 8 -> fragment LDS.64 conflict-free).  tf32 hi/lo split in
// registers; lo term passed un-cvt'd (HW reads tf32 bits only).
// ---------------------------------------------------------------------------

#define NN 100000
#define NE 1600000

__device__ __align__(128) float g_bufA[(size_t)NN * 128];
__device__ __align__(128) float g_bufB[(size_t)NN * 128];
__device__ __align__(128) float g_dinv[NN];
__device__ __align__(128) int   g_degc[NN];
__device__ __align__(128) int   g_rows[NN + 1];
__device__ __align__(128) int   g_curs[NN];
__device__ __align__(128) int   g_csr [NE];
__device__ __align__(128) int   g_bsum[256];
__device__ __align__(128) int   g_boff[256];

// ------------------------------------------------------------------ CSR build
__global__ void zero_int_kernel(int* __restrict__ p, int n) {
    int i = blockIdx.x * blockDim.x + threadIdx.x;
    if (i < n) p[i] = 0;
}

__global__ void count_kernel(const int* __restrict__ dst, int* __restrict__ cnt, int e) {
    int i = blockIdx.x * blockDim.x + threadIdx.x;
    if (i < e) atomicAdd(&cnt[dst[i]], 1);
}

__global__ void dinv_kernel(const int* __restrict__ cnt, float* __restrict__ dinv, int n) {
    int i = blockIdx.x * blockDim.x + threadIdx.x;
    if (i < n) dinv[i] = rsqrtf((float)(1 + cnt[i]));
}

__global__ __launch_bounds__(1024)
void scan_local_kernel(const int* __restrict__ deg, int* __restrict__ row_start,
                       int* __restrict__ bsum, int n) {
    __shared__ int wsum[32];
    const int tid = threadIdx.x, lane = tid & 31, wid = tid >> 5;
    const int i = blockIdx.x * 1024 + tid;
    int v = (i < n) ? deg[i] : 0;
    int x = v;
#pragma unroll
    for (int d = 1; d < 32; d <<= 1) {
        int y = __shfl_up_sync(0xffffffffu, x, d);
        if (lane >= d) x += y;
    }
    if (lane == 31) wsum[wid] = x;
    __syncthreads();
    if (wid == 0) {
        int s = wsum[lane];
#pragma unroll
        for (int d = 1; d < 32; d <<= 1) {
            int y = __shfl_up_sync(0xffffffffu, s, d);
            if (lane >= d) s += y;
        }
        wsum[lane] = s;
    }
    __syncthreads();
    int excl = (x - v) + (wid > 0 ? wsum[wid - 1] : 0);
    if (i < n) row_start[i] = excl;
    if (tid == 1023) bsum[blockIdx.x] = excl + v;
}

__global__ __launch_bounds__(128)
void scan_block_kernel(const int* __restrict__ bsum, int* __restrict__ boff,
                       int* __restrict__ row_start, int nb, int n) {
    __shared__ int carry_s;
    const int tid = threadIdx.x, lane = tid & 31;
    if (tid == 0) carry_s = 0;
    __syncthreads();
    for (int base = 0; base < nb; base += 32) {
        if (tid < 32) {
            int j = base + lane;
            int v = (j < nb) ? bsum[j] : 0;
            int x = v;
#pragma unroll
            for (int d = 1; d < 32; d <<= 1) {
                int y = __shfl_up_sync(0xffffffffu, x, d);
                if (lane >= d) x += y;
            }
            int carry = carry_s;
            if (j < nb) boff[j] = carry + (x - v);
            if (lane == 31) carry_s = carry + x;
        }
        __syncthreads();
    }
    if (tid == 0) row_start[n] = carry_s;
}

__global__ __launch_bounds__(1024)
void scan_add_kernel(int* __restrict__ row_start, int* __restrict__ cursor,
                     const int* __restrict__ boff, int n) {
    int i = blockIdx.x * 1024 + threadIdx.x;
    if (i < n) {
        int v = row_start[i] + boff[blockIdx.x];
        row_start[i] = v;
        cursor[i]    = v;
    }
}

__global__ void place_kernel(const int* __restrict__ src, const int* __restrict__ dst,
                             int* __restrict__ cursor, int* __restrict__ csr_src, int e) {
    int i = blockIdx.x * blockDim.x + threadIdx.x;
    if (i < e) {
        int pos = atomicAdd(&cursor[dst[i]], 1);
        csr_src[pos] = src[i];
    }
}

// ------------------------------------------------------------ tf32x3 GEMM
// out[m][c] = dinv[m] * sum_k X[m][k] * W[k][c]
// Smem rows hold 64 float2 pairs (v[k], v[k+4]); stride LD2=136 floats
// (136 mod 32 = 8): fragment LDS.64 banks (g*8 + c*2) mod 32, conflict-free.
// hi = cvt.rna.tf32(v); lo = v - hi passed raw (HW uses tf32 bits only).

__device__ __forceinline__ float to_tf32(float x) {
    uint32_t u;
    asm("cvt.rna.tf32.f32 %0, %1;" : "=r"(u) : "f"(x));
    return __uint_as_float(u);
}

__device__ __forceinline__ void split_tf32(float v, uint32_t& h, uint32_t& l) {
    float hf = to_tf32(v);
    h = __float_as_uint(hf);
    l = __float_as_uint(v - hf);    // no second cvt: tf32 HW truncates
}

#define MMA_TF32(acc, a, b)                                                   \
    asm volatile(                                                             \
        "mma.sync.aligned.m16n8k8.row.col.f32.tf32.tf32.f32 "                 \
        "{%0,%1,%2,%3}, {%4,%5,%6,%7}, {%8,%9}, {%0,%1,%2,%3};"               \
        : "+f"((acc)[0]), "+f"((acc)[1]), "+f"((acc)[2]), "+f"((acc)[3])      \
        : "r"((a)[0]), "r"((a)[1]), "r"((a)[2]), "r"((a)[3]),                 \
          "r"((b)[0]), "r"((b)[1]))

template <int BN>
__global__ __launch_bounds__(256)
void gemm_tf32_kernel(const float* __restrict__ X, const float* __restrict__ W,
                      const float* __restrict__ dinv,
                      float* __restrict__ out, int M) {
    constexpr int BM  = 64;
    constexpr int LD2 = 136;         // floats per row (128 payload + 8 pad)
    constexpr int NT  = BN / 32;

    extern __shared__ float smem[];
    float* Xs = smem;                // [BM][LD2]
    float* Ws = Xs + BM * LD2;       // [BN][LD2] (n-major)

    const int tid       = threadIdx.x;
    const int block_row = blockIdx.x * BM;

    // stage X: pair layout. warp covers one row's p=0..31 -> STS.64 banks 2p.
    for (int i = tid; i < BM * 64; i += 256) {
        int r = i >> 6, p = i & 63;
        int k0 = ((p >> 2) << 3) + (p & 3);
        int gr = block_row + r;
        float v0 = 0.f, v1 = 0.f;
        if (gr < M) {
            v0 = X[(size_t)gr * 128 + k0];
            v1 = X[(size_t)gr * 128 + k0 + 4];
        }
        *(float2*)&Xs[r * LD2 + p * 2] = make_float2(v0, v1);
    }
    // stage W (k-major global -> n-major pair rows); LDGs coalesced along n.
    for (int i = tid; i < BN * 64; i += 256) {
        int n = i % BN, p = i / BN;
        int k0 = ((p >> 2) << 3) + (p & 3);
        float v0 = W[k0 * BN + n];
        float v1 = W[(k0 + 4) * BN + n];
        *(float2*)&Ws[n * LD2 + p * 2] = make_float2(v0, v1);
    }
    __syncthreads();

    const int lane = tid & 31, wid = tid >> 5;
    const int wm = wid & 1, wn = wid >> 1;
    const int m_base = wm * 32;
    const int n_base = wn * (BN / 4);
    const int g = lane >> 2, c = lane & 3;

    float acc[2][NT][4];
#pragma unroll
    for (int mt = 0; mt < 2; mt++)
#pragma unroll
        for (int nt = 0; nt < NT; nt++)
#pragma unroll
            for (int r = 0; r < 4; r++) acc[mt][nt][r] = 0.f;

#pragma unroll
    for (int ks = 0; ks < 16; ks++) {
        const int poff = ks * 8 + c * 2;
        uint32_t ah[2][4], al[2][4];
#pragma unroll
        for (int mt = 0; mt < 2; mt++) {
            float2 f0 = *(const float2*)&Xs[(m_base + mt * 16 + g) * LD2 + poff];
            float2 f1 = *(const float2*)&Xs[(m_base + mt * 16 + g + 8) * LD2 + poff];
            split_tf32(f0.x, ah[mt][0], al[mt][0]);
            split_tf32(f1.x, ah[mt][1], al[mt][1]);
            split_tf32(f0.y, ah[mt][2], al[mt][2]);
            split_tf32(f1.y, ah[mt][3], al[mt][3]);
        }
        uint32_t bh[NT][2], bl[NT][2];
#pragma unroll
        for (int nt = 0; nt < NT; nt++) {
            float2 fb = *(const float2*)&Ws[(n_base + nt * 8 + g) * LD2 + poff];
            split_tf32(fb.x, bh[nt][0], bl[nt][0]);
            split_tf32(fb.y, bh[nt][1], bl[nt][1]);
        }
#pragma unroll
        for (int mt = 0; mt < 2; mt++)
#pragma unroll
            for (int nt = 0; nt < NT; nt++) {
                MMA_TF32(acc[mt][nt], ah[mt], bh[nt]);
                MMA_TF32(acc[mt][nt], ah[mt], bl[nt]);
                MMA_TF32(acc[mt][nt], al[mt], bh[nt]);
            }
    }

    // epilogue: scale by dinv[row], store float2 pairs
#pragma unroll
    for (int mt = 0; mt < 2; mt++) {
        int row0 = block_row + m_base + mt * 16 + g;
        int row1 = row0 + 8;
        float dv0 = (row0 < M) ? dinv[row0] : 0.f;
        float dv1 = (row1 < M) ? dinv[row1] : 0.f;
#pragma unroll
        for (int nt = 0; nt < NT; nt++) {
            int col = n_base + nt * 8 + 2 * c;
            if (row0 < M) {
                float2 o = make_float2(acc[mt][nt][0] * dv0, acc[mt][nt][1] * dv0);
                *(float2*)&out[(size_t)row0 * BN + col] = o;
            }
            if (row1 < M) {
                float2 o = make_float2(acc[mt][nt][2] * dv1, acc[mt][nt][3] * dv1);
                *(float2*)&out[(size_t)row1 * BN + col] = o;
            }
        }
    }
}

// -------------------------------------------------- gather + fused epilogue
__global__ void gather128_kernel(const float* __restrict__ A,
                                 const int* __restrict__ row_start,
                                 const int* __restrict__ csr_src,
                                 const float* __restrict__ dinv,
                                 const float* __restrict__ bias,
                                 float* __restrict__ out, int N) {
    int idx  = blockIdx.x * blockDim.x + threadIdx.x;
    int d    = idx >> 5;
    int lane = idx & 31;
    if (d >= N) return;
    const float4* A4 = (const float4*)A;
    float4 acc = A4[(size_t)d * 32 + lane];          // self loop
    int rs = row_start[d], re = row_start[d + 1];
    int j = rs;
    for (; j + 1 < re; j += 2) {
        int s0 = csr_src[j], s1 = csr_src[j + 1];
        float4 v0 = A4[(size_t)s0 * 32 + lane];
        float4 v1 = A4[(size_t)s1 * 32 + lane];
        acc.x += v0.x; acc.y += v0.y; acc.z += v0.z; acc.w += v0.w;
        acc.x += v1.x; acc.y += v1.y; acc.z += v1.z; acc.w += v1.w;
    }
    if (j < re) {
        float4 v = A4[(size_t)csr_src[j] * 32 + lane];
        acc.x += v.x; acc.y += v.y; acc.z += v.z; acc.w += v.w;
    }
    float  dv = dinv[d];
    float4 b  = ((const float4*)bias)[lane];
    float4 o;
    o.x = fmaxf(fmaf(acc.x, dv, b.x), 0.f);
    o.y = fmaxf(fmaf(acc.y, dv, b.y), 0.f);
    o.z = fmaxf(fmaf(acc.z, dv, b.z), 0.f);
    o.w = fmaxf(fmaf(acc.w, dv, b.w), 0.f);
    ((float4*)out)[(size_t)d * 32 + lane] = o;
}

__global__ void gather64_kernel(const float* __restrict__ A,
                                const int* __restrict__ row_start,
                                const int* __restrict__ csr_src,
                                const float* __restrict__ dinv,
                                const float* __restrict__ bias,
                                float* __restrict__ out, int N) {
    int idx  = blockIdx.x * blockDim.x + threadIdx.x;
    int d    = idx >> 5;
    int lane = idx & 31;
    if (d >= N) return;
    const float2* A2 = (const float2*)A;
    float2 acc = A2[(size_t)d * 32 + lane];          // self loop
    int rs = row_start[d], re = row_start[d + 1];
    int j = rs;
    for (; j + 1 < re; j += 2) {
        int s0 = csr_src[j], s1 = csr_src[j + 1];
        float2 v0 = A2[(size_t)s0 * 32 + lane];
        float2 v1 = A2[(size_t)s1 * 32 + lane];
        acc.x += v0.x; acc.y += v0.y;
        acc.x += v1.x; acc.y += v1.y;
    }
    if (j < re) {
        float2 v = A2[(size_t)csr_src[j] * 32 + lane];
        acc.x += v.x; acc.y += v.y;
    }
    float  dv = dinv[d];
    float2 b  = ((const float2*)bias)[lane];
    float2 o;
    o.x = fmaxf(fmaf(acc.x, dv, b.x), 0.f);
    o.y = fmaxf(fmaf(acc.y, dv, b.y), 0.f);
    ((float2*)out)[(size_t)d * 32 + lane] = o;
}

// -------------------------------------------------------------------- launch
extern "C" void kernel_launch(void* const* d_in, const int* in_sizes, int n_in,
                              void* d_out, int out_size) {
    const float* x   = (const float*)d_in[0];
    const int*   ei  = (const int*)d_in[1];     // int32 (JAX x64 disabled)
    const float* W1  = (const float*)d_in[2];
    const float* b1  = (const float*)d_in[3];
    const float* W2  = (const float*)d_in[4];
    const float* b2  = (const float*)d_in[5];
    float*       out = (float*)d_out;

    const int N = in_sizes[0] / 128;
    const int E = in_sizes[1] / 2;
    const int* esrc = ei;
    const int* edst = ei + E;

    float *bufA, *bufB, *dinv;
    int *degc, *rows, *curs, *csr, *bsum, *boff;
    cudaGetSymbolAddress((void**)&bufA, g_bufA);
    cudaGetSymbolAddress((void**)&bufB, g_bufB);
    cudaGetSymbolAddress((void**)&dinv, g_dinv);
    cudaGetSymbolAddress((void**)&degc, g_degc);
    cudaGetSymbolAddress((void**)&rows, g_rows);
    cudaGetSymbolAddress((void**)&curs, g_curs);
    cudaGetSymbolAddress((void**)&csr,  g_csr);
    cudaGetSymbolAddress((void**)&bsum, g_bsum);
    cudaGetSymbolAddress((void**)&boff, g_boff);

    constexpr int SMEM1 = (64 + 128) * 136 * 4;  // 104448 -> 2 CTAs/SM
    constexpr int SMEM2 = (64 + 64)  * 136 * 4;  // 69632  -> 3 CTAs/SM
    cudaFuncSetAttribute(gemm_tf32_kernel<128>,
                         cudaFuncAttributeMaxDynamicSharedMemorySize, SMEM1);
    cudaFuncSetAttribute(gemm_tf32_kernel<64>,
                         cudaFuncAttributeMaxDynamicSharedMemorySize, SMEM2);

    const int NB = (N + 1023) / 1024;   // scan blocks (98)

    // Launch order: gemm1 is launch #4 (ncu profiles launch #4).
    zero_int_kernel<<<(N + 255) / 256, 256>>>(degc, N);                          // 1
    count_kernel<<<(E + 255) / 256, 256>>>(edst, degc, E);                       // 2
    dinv_kernel<<<(N + 255) / 256, 256>>>(degc, dinv, N);                        // 3
    gemm_tf32_kernel<128><<<(N + 63) / 64, 256, SMEM1>>>(x, W1, dinv, bufA, N);  // 4
    scan_local_kernel<<<NB, 1024>>>(degc, rows, bsum, N);                        // 5
    scan_block_kernel<<<1, 128>>>(bsum, boff, rows, NB, N);                      // 6
    scan_add_kernel<<<NB, 1024>>>(rows, curs, boff, N);                          // 7
    place_kernel<<<(E + 255) / 256, 256>>>(esrc, edst, curs, csr, E);            // 8
    {
        long long t = (long long)N * 32;
        gather128_kernel<<<(unsigned)((t + 255) / 256), 256>>>(bufA, rows, csr, dinv, b1, bufB, N);
    }
    gemm_tf32_kernel<64><<<(N + 63) / 64, 256, SMEM2>>>(bufB, W2, dinv, bufA, N);
    {
        long long t = (long long)N * 32;
        gather64_kernel<<<(unsigned)((t + 255) / 256), 256>>>(bufA, rows, csr, dinv, b2, out, N);
    }
}

// round 17
// speedup vs baseline: 1.1187x; 1.1187x over previous
#include <cuda_runtime.h>
#include <cuda_bf16.h>
#include <cstdint>

// ---------------------------------------------------------------------------
// 2-layer GCN, CSR-by-dst gather formulation:
//   deg[i] = 1 + in_degree(i);  dinv = rsqrt(deg)
//   h' = dinv ⊙ (X @ W)            (tf32x3 tensor-core GEMM, scaled write)
//   out[d] = relu(dinv[d] * (h'[d] + sum_{s in nbr(d)} h'[s]) + b)   (gather)
// Round-15 kernels (best: 285us) + fork: CSR scan/place chain overlaps gemm1
// on a second stream (graph-captured via event edges).
// ---------------------------------------------------------------------------

#define NN 100000
#define NE 1600000

__device__ __align__(128) float g_bufA[(size_t)NN * 128];
__device__ __align__(128) float g_bufB[(size_t)NN * 128];
__device__ __align__(128) float g_dinv[NN];
__device__ __align__(128) int   g_degc[NN];
__device__ __align__(128) int   g_rows[NN + 1];
__device__ __align__(128) int   g_curs[NN];
__device__ __align__(128) int   g_csr [NE];
__device__ __align__(128) int   g_bsum[256];
__device__ __align__(128) int   g_boff[256];

// ------------------------------------------------------------------ CSR build
__global__ void zero_int_kernel(int* __restrict__ p, int n) {
    int i = blockIdx.x * blockDim.x + threadIdx.x;
    if (i < n) p[i] = 0;
}

__global__ void count_kernel(const int* __restrict__ dst, int* __restrict__ cnt, int e) {
    int i = blockIdx.x * blockDim.x + threadIdx.x;
    if (i < e) atomicAdd(&cnt[dst[i]], 1);
}

__global__ void dinv_kernel(const int* __restrict__ cnt, float* __restrict__ dinv, int n) {
    int i = blockIdx.x * blockDim.x + threadIdx.x;
    if (i < n) dinv[i] = rsqrtf((float)(1 + cnt[i]));
}

__global__ __launch_bounds__(1024)
void scan_local_kernel(const int* __restrict__ deg, int* __restrict__ row_start,
                       int* __restrict__ bsum, int n) {
    __shared__ int wsum[32];
    const int tid = threadIdx.x, lane = tid & 31, wid = tid >> 5;
    const int i = blockIdx.x * 1024 + tid;
    int v = (i < n) ? deg[i] : 0;
    int x = v;
#pragma unroll
    for (int d = 1; d < 32; d <<= 1) {
        int y = __shfl_up_sync(0xffffffffu, x, d);
        if (lane >= d) x += y;
    }
    if (lane == 31) wsum[wid] = x;
    __syncthreads();
    if (wid == 0) {
        int s = wsum[lane];
#pragma unroll
        for (int d = 1; d < 32; d <<= 1) {
            int y = __shfl_up_sync(0xffffffffu, s, d);
            if (lane >= d) s += y;
        }
        wsum[lane] = s;
    }
    __syncthreads();
    int excl = (x - v) + (wid > 0 ? wsum[wid - 1] : 0);
    if (i < n) row_start[i] = excl;
    if (tid == 1023) bsum[blockIdx.x] = excl + v;
}

__global__ __launch_bounds__(128)
void scan_block_kernel(const int* __restrict__ bsum, int* __restrict__ boff,
                       int* __restrict__ row_start, int nb, int n) {
    __shared__ int carry_s;
    const int tid = threadIdx.x, lane = tid & 31;
    if (tid == 0) carry_s = 0;
    __syncthreads();
    for (int base = 0; base < nb; base += 32) {
        if (tid < 32) {
            int j = base + lane;
            int v = (j < nb) ? bsum[j] : 0;
            int x = v;
#pragma unroll
            for (int d = 1; d < 32; d <<= 1) {
                int y = __shfl_up_sync(0xffffffffu, x, d);
                if (lane >= d) x += y;
            }
            int carry = carry_s;
            if (j < nb) boff[j] = carry + (x - v);
            if (lane == 31) carry_s = carry + x;
        }
        __syncthreads();
    }
    if (tid == 0) row_start[n] = carry_s;
}

__global__ __launch_bounds__(1024)
void scan_add_kernel(int* __restrict__ row_start, int* __restrict__ cursor,
                     const int* __restrict__ boff, int n) {
    int i = blockIdx.x * 1024 + threadIdx.x;
    if (i < n) {
        int v = row_start[i] + boff[blockIdx.x];
        row_start[i] = v;
        cursor[i]    = v;
    }
}

__global__ void place_kernel(const int* __restrict__ src, const int* __restrict__ dst,
                             int* __restrict__ cursor, int* __restrict__ csr_src, int e) {
    int i = blockIdx.x * blockDim.x + threadIdx.x;
    if (i < e) {
        int pos = atomicAdd(&cursor[dst[i]], 1);
        csr_src[pos] = src[i];
    }
}

// ------------------------------------------------------------ tf32x3 GEMM
// out[m][c] = dinv[m] * sum_k X[m][k] * W[k][c]
// Plain fp32 smem; hi/lo split in registers at fragment load.
// LD=132: fragment LDS bank = 4g + c, conflict-free.
// BM=64, K=128. 256 threads = 8 warps as 2(m) x 4(n); warp tile 32 x (BN/4).

__device__ __forceinline__ float to_tf32(float x) {
    uint32_t u;
    asm("cvt.rna.tf32.f32 %0, %1;" : "=r"(u) : "f"(x));
    return __uint_as_float(u);
}

__device__ __forceinline__ void split_tf32(float v, uint32_t& h, uint32_t& l) {
    float hf = to_tf32(v);
    h = __float_as_uint(hf);
    l = __float_as_uint(to_tf32(v - hf));
}

#define MMA_TF32(acc, a, b)                                                   \
    asm volatile(                                                             \
        "mma.sync.aligned.m16n8k8.row.col.f32.tf32.tf32.f32 "                 \
        "{%0,%1,%2,%3}, {%4,%5,%6,%7}, {%8,%9}, {%0,%1,%2,%3};"               \
        : "+f"((acc)[0]), "+f"((acc)[1]), "+f"((acc)[2]), "+f"((acc)[3])      \
        : "r"((a)[0]), "r"((a)[1]), "r"((a)[2]), "r"((a)[3]),                 \
          "r"((b)[0]), "r"((b)[1]))

template <int BN>
__global__ __launch_bounds__(256)
void gemm_tf32_kernel(const float* __restrict__ X, const float* __restrict__ W,
                      const float* __restrict__ dinv,
                      float* __restrict__ out, int M) {
    constexpr int K  = 128;
    constexpr int BM = 64;
    constexpr int LD = 132;
    constexpr int NT = BN / 32;

    extern __shared__ float smem[];
    float* Xs = smem;                // [BM][LD] fp32
    float* Ws = Xs + BM * LD;        // [BN][LD] fp32 (n-major)

    const int tid       = threadIdx.x;
    const int block_row = blockIdx.x * BM;

    // stage X tile (fp32, float4 copies)
    for (int i = tid; i < BM * (K / 4); i += 256) {
        int r = i >> 5, c4 = i & 31;
        int gr = block_row + r;
        float4 v = make_float4(0.f, 0.f, 0.f, 0.f);
        if (gr < M) v = ((const float4*)X)[(size_t)gr * 32 + c4];
        *(float4*)&Xs[r * LD + 4 * c4] = v;
    }
    // stage W transposed (n-major, fp32)
    for (int i = tid; i < K * BN; i += 256) {
        int k = i / BN, n = i % BN;      // consecutive tid -> consecutive n
        Ws[n * LD + k] = W[i];
    }
    __syncthreads();

    const int lane = tid & 31, wid = tid >> 5;
    const int wm = wid & 1, wn = wid >> 1;
    const int m_base = wm * 32;
    const int n_base = wn * (BN / 4);
    const int g = lane >> 2, c = lane & 3;

    float acc[2][NT][4];
#pragma unroll
    for (int mt = 0; mt < 2; mt++)
#pragma unroll
        for (int nt = 0; nt < NT; nt++)
#pragma unroll
            for (int r = 0; r < 4; r++) acc[mt][nt][r] = 0.f;

#pragma unroll
    for (int ks = 0; ks < K; ks += 8) {
        uint32_t ah[2][4], al[2][4];
#pragma unroll
        for (int mt = 0; mt < 2; mt++) {
            const float* p = &Xs[(m_base + mt * 16 + g) * LD + ks + c];
            split_tf32(p[0],          ah[mt][0], al[mt][0]);
            split_tf32(p[8 * LD],     ah[mt][1], al[mt][1]);
            split_tf32(p[4],          ah[mt][2], al[mt][2]);
            split_tf32(p[8 * LD + 4], ah[mt][3], al[mt][3]);
        }
        uint32_t bh[NT][2], bl[NT][2];
#pragma unroll
        for (int nt = 0; nt < NT; nt++) {
            const float* q = &Ws[(n_base + nt * 8 + g) * LD + ks + c];
            split_tf32(q[0], bh[nt][0], bl[nt][0]);
            split_tf32(q[4], bh[nt][1], bl[nt][1]);
        }
#pragma unroll
        for (int mt = 0; mt < 2; mt++)
#pragma unroll
            for (int nt = 0; nt < NT; nt++) {
                MMA_TF32(acc[mt][nt], ah[mt], bh[nt]);
                MMA_TF32(acc[mt][nt], ah[mt], bl[nt]);
                MMA_TF32(acc[mt][nt], al[mt], bh[nt]);
            }
    }

    // epilogue: scale by dinv[row], store float2 pairs
#pragma unroll
    for (int mt = 0; mt < 2; mt++) {
        int row0 = block_row + m_base + mt * 16 + g;
        int row1 = row0 + 8;
        float dv0 = (row0 < M) ? dinv[row0] : 0.f;
        float dv1 = (row1 < M) ? dinv[row1] : 0.f;
#pragma unroll
        for (int nt = 0; nt < NT; nt++) {
            int col = n_base + nt * 8 + 2 * c;
            if (row0 < M) {
                float2 o = make_float2(acc[mt][nt][0] * dv0, acc[mt][nt][1] * dv0);
                *(float2*)&out[(size_t)row0 * BN + col] = o;
            }
            if (row1 < M) {
                float2 o = make_float2(acc[mt][nt][2] * dv1, acc[mt][nt][3] * dv1);
                *(float2*)&out[(size_t)row1 * BN + col] = o;
            }
        }
    }
}

// -------------------------------------------------- gather + fused epilogue
__global__ void gather128_kernel(const float* __restrict__ A,
                                 const int* __restrict__ row_start,
                                 const int* __restrict__ csr_src,
                                 const float* __restrict__ dinv,
                                 const float* __restrict__ bias,
                                 float* __restrict__ out, int N) {
    int idx  = blockIdx.x * blockDim.x + threadIdx.x;
    int d    = idx >> 5;
    int lane = idx & 31;
    if (d >= N) return;
    const float4* A4 = (const float4*)A;
    float4 acc = A4[(size_t)d * 32 + lane];          // self loop
    int rs = row_start[d], re = row_start[d + 1];
    int j = rs;
    for (; j + 1 < re; j += 2) {
        int s0 = csr_src[j], s1 = csr_src[j + 1];
        float4 v0 = A4[(size_t)s0 * 32 + lane];
        float4 v1 = A4[(size_t)s1 * 32 + lane];
        acc.x += v0.x; acc.y += v0.y; acc.z += v0.z; acc.w += v0.w;
        acc.x += v1.x; acc.y += v1.y; acc.z += v1.z; acc.w += v1.w;
    }
    if (j < re) {
        float4 v = A4[(size_t)csr_src[j] * 32 + lane];
        acc.x += v.x; acc.y += v.y; acc.z += v.z; acc.w += v.w;
    }
    float  dv = dinv[d];
    float4 b  = ((const float4*)bias)[lane];
    float4 o;
    o.x = fmaxf(fmaf(acc.x, dv, b.x), 0.f);
    o.y = fmaxf(fmaf(acc.y, dv, b.y), 0.f);
    o.z = fmaxf(fmaf(acc.z, dv, b.z), 0.f);
    o.w = fmaxf(fmaf(acc.w, dv, b.w), 0.f);
    ((float4*)out)[(size_t)d * 32 + lane] = o;
}

__global__ void gather64_kernel(const float* __restrict__ A,
                                const int* __restrict__ row_start,
                                const int* __restrict__ csr_src,
                                const float* __restrict__ dinv,
                                const float* __restrict__ bias,
                                float* __restrict__ out, int N) {
    int idx  = blockIdx.x * blockDim.x + threadIdx.x;
    int d    = idx >> 5;
    int lane = idx & 31;
    if (d >= N) return;
    const float2* A2 = (const float2*)A;
    float2 acc = A2[(size_t)d * 32 + lane];          // self loop
    int rs = row_start[d], re = row_start[d + 1];
    int j = rs;
    for (; j + 1 < re; j += 2) {
        int s0 = csr_src[j], s1 = csr_src[j + 1];
        float2 v0 = A2[(size_t)s0 * 32 + lane];
        float2 v1 = A2[(size_t)s1 * 32 + lane];
        acc.x += v0.x; acc.y += v0.y;
        acc.x += v1.x; acc.y += v1.y;
    }
    if (j < re) {
        float2 v = A2[(size_t)csr_src[j] * 32 + lane];
        acc.x += v.x; acc.y += v.y;
    }
    float  dv = dinv[d];
    float2 b  = ((const float2*)bias)[lane];
    float2 o;
    o.x = fmaxf(fmaf(acc.x, dv, b.x), 0.f);
    o.y = fmaxf(fmaf(acc.y, dv, b.y), 0.f);
    ((float2*)out)[(size_t)d * 32 + lane] = o;
}

// -------------------------------------------------------------------- launch
extern "C" void kernel_launch(void* const* d_in, const int* in_sizes, int n_in,
                              void* d_out, int out_size) {
    const float* x   = (const float*)d_in[0];
    const int*   ei  = (const int*)d_in[1];     // int32 (JAX x64 disabled)
    const float* W1  = (const float*)d_in[2];
    const float* b1  = (const float*)d_in[3];
    const float* W2  = (const float*)d_in[4];
    const float* b2  = (const float*)d_in[5];
    float*       out = (float*)d_out;

    const int N = in_sizes[0] / 128;
    const int E = in_sizes[1] / 2;
    const int* esrc = ei;
    const int* edst = ei + E;

    float *bufA, *bufB, *dinv;
    int *degc, *rows, *curs, *csr, *bsum, *boff;
    cudaGetSymbolAddress((void**)&bufA, g_bufA);
    cudaGetSymbolAddress((void**)&bufB, g_bufB);
    cudaGetSymbolAddress((void**)&dinv, g_dinv);
    cudaGetSymbolAddress((void**)&degc, g_degc);
    cudaGetSymbolAddress((void**)&rows, g_rows);
    cudaGetSymbolAddress((void**)&curs, g_curs);
    cudaGetSymbolAddress((void**)&csr,  g_csr);
    cudaGetSymbolAddress((void**)&bsum, g_bsum);
    cudaGetSymbolAddress((void**)&boff, g_boff);

    constexpr int SMEM1 = (64 + 128) * 132 * 4;  // 101376 -> 2 CTAs/SM
    constexpr int SMEM2 = (64 + 64)  * 132 * 4;  // 67584  -> 3 CTAs/SM
    cudaFuncSetAttribute(gemm_tf32_kernel<128>,
                         cudaFuncAttributeMaxDynamicSharedMemorySize, SMEM1);
    cudaFuncSetAttribute(gemm_tf32_kernel<64>,
                         cudaFuncAttributeMaxDynamicSharedMemorySize, SMEM2);

    const int NB = (N + 1023) / 1024;   // scan blocks (98)

    // Side stream + events (created once; never destroyed so graph-referenced
    // handles stay valid; per-call device work is identical).
    static cudaStream_t s2 = nullptr;
    static cudaEvent_t  evFork = nullptr, evJoin = nullptr;
    if (s2 == nullptr) {
        cudaStreamCreateWithFlags(&s2, cudaStreamNonBlocking);
        cudaEventCreateWithFlags(&evFork, cudaEventDisableTiming);
        cudaEventCreateWithFlags(&evJoin, cudaEventDisableTiming);
    }

    // ---- serial prelude (both branches need degc/dinv)
    zero_int_kernel<<<(N + 255) / 256, 256>>>(degc, N);                          // 1
    count_kernel<<<(E + 255) / 256, 256>>>(edst, degc, E);                       // 2
    dinv_kernel<<<(N + 255) / 256, 256>>>(degc, dinv, N);                        // 3

    // ---- fork: gemm1 on origin stream (launch #4), CSR chain on s2
    cudaEventRecord(evFork, 0);
    gemm_tf32_kernel<128><<<(N + 63) / 64, 256, SMEM1>>>(x, W1, dinv, bufA, N);  // 4

    cudaStreamWaitEvent(s2, evFork, 0);
    scan_local_kernel<<<NB, 1024, 0, s2>>>(degc, rows, bsum, N);
    scan_block_kernel<<<1, 128, 0, s2>>>(bsum, boff, rows, NB, N);
    scan_add_kernel<<<NB, 1024, 0, s2>>>(rows, curs, boff, N);
    place_kernel<<<(E + 255) / 256, 256, 0, s2>>>(esrc, edst, curs, csr, E);
    cudaEventRecord(evJoin, s2);

    // ---- join: gather needs bufA (origin) + CSR (s2)
    cudaStreamWaitEvent(0, evJoin, 0);
    {
        long long t = (long long)N * 32;
        gather128_kernel<<<(unsigned)((t + 255) / 256), 256>>>(bufA, rows, csr, dinv, b1, bufB, N);
    }
    gemm_tf32_kernel<64><<<(N + 63) / 64, 256, SMEM2>>>(bufB, W2, dinv, bufA, N);
    {
        long long t = (long long)N * 32;
        gather64_kernel<<<(unsigned)((t + 255) / 256), 256>>>(bufA, rows, csr, dinv, b2, out, N);
    }
}